// round 9
// baseline (speedup 1.0000x reference)
#include <cuda_runtime.h>
#include <cuda_fp16.h>
#include <cstdint>

#define THREADS 256
#define TB 8
#define NJ 12
#define DM 128
#define NH 4
#define HD 32
#define MR 96              // rows per CTA = TB*NJ

#define TSTR 136           // fp16 tile stride (halves)
#define QSTR 104           // fp16 QKV stride (halves)

// smem byte offsets
#define OFF_X    0                         // 96 x 136 h = 26112
#define OFF_QKV  26112                     // 96 x 104 h = 19968
#define OFF_AO   46080                     // 96 x 136 h = 26112
#define OFF_WO   0                         // 128 x 136 h = 34816 (overlays X|QKV, post-loop)
#define OFF_BQ   72192
#define OFF_BK   72704
#define OFF_BV   73216
#define OFF_BO   73728
#define OFF_ADJ  74240                     // 144 f32
#define OFF_KM   74816                     // 96 f32
#define SMEM_BYTES 75200                   // 3 CTAs/SM (225.6 KB)

// pre-converted weights: Wq|Wk|Wv stacked rows, then Wo
__device__ __half gWqkv[3 * DM * DM];      // [384][128]
__device__ __half gWo[DM * DM];            // [128][128]

__device__ __forceinline__ uint2 f4_to_h4(float4 v) {
    __half2 a = __floats2half2_rn(v.x, v.y);
    __half2 b = __floats2half2_rn(v.z, v.w);
    uint2 r;
    r.x = *(uint32_t*)&a; r.y = *(uint32_t*)&b;
    return r;
}

__global__ void convert_weights(const float* __restrict__ Wq, const float* __restrict__ Wk,
                                const float* __restrict__ Wv, const float* __restrict__ Wo) {
    int i = blockIdx.x * 256 + threadIdx.x;        // 0..4095 (float4 index per 16384-array)
    *(uint2*)(gWqkv + 0*16384 + i*4) = f4_to_h4(((const float4*)Wq)[i]);
    *(uint2*)(gWqkv + 1*16384 + i*4) = f4_to_h4(((const float4*)Wk)[i]);
    *(uint2*)(gWqkv + 2*16384 + i*4) = f4_to_h4(((const float4*)Wv)[i]);
    *(uint2*)(gWo + i*4)             = f4_to_h4(((const float4*)Wo)[i]);
}

__device__ __forceinline__ void ldsm_x4(uint32_t* r, uint32_t addr) {
    asm volatile("ldmatrix.sync.aligned.m8n8.x4.shared.b16 {%0,%1,%2,%3}, [%4];"
        : "=r"(r[0]), "=r"(r[1]), "=r"(r[2]), "=r"(r[3]) : "r"(addr));
}
__device__ __forceinline__ void mma16(float* d, const uint32_t* a, const uint32_t* b) {
    asm volatile(
        "mma.sync.aligned.m16n8k16.row.col.f32.f16.f16.f32 "
        "{%0,%1,%2,%3}, {%4,%5,%6,%7}, {%8,%9}, {%0,%1,%2,%3};"
        : "+f"(d[0]), "+f"(d[1]), "+f"(d[2]), "+f"(d[3])
        : "r"(a[0]), "r"(a[1]), "r"(a[2]), "r"(a[3]), "r"(b[0]), "r"(b[1]));
}

__global__ void __launch_bounds__(THREADS, 3)
cross_joint_attn_kernel(
    const float* __restrict__ x, const float* __restrict__ vis,
    const float* __restrict__ bq, const float* __restrict__ bk,
    const float* __restrict__ bv, const float* __restrict__ bo,
    const float* __restrict__ bias_scale, const float* __restrict__ adj,
    float* __restrict__ out)
{
    extern __shared__ __align__(16) char smc[];
    __half* Xh  = (__half*)(smc + OFF_X);
    __half* QKV = (__half*)(smc + OFF_QKV);
    __half* AOh = (__half*)(smc + OFF_AO);
    __half* WOh = (__half*)(smc + OFF_WO);
    float* bqs  = (float*)(smc + OFF_BQ);
    float* bks  = (float*)(smc + OFF_BK);
    float* bvs  = (float*)(smc + OFF_BV);
    float* bos  = (float*)(smc + OFF_BO);
    float* adjb = (float*)(smc + OFF_ADJ);
    float* kmsk = (float*)(smc + OFF_KM);

    const int tid  = threadIdx.x;
    const int lane = tid & 31;
    const int warp = tid >> 5;
    const int cta  = blockIdx.x;
    const int gid  = lane >> 2;
    const int tig  = lane & 3;

    const uint32_t sb   = (uint32_t)__cvta_generic_to_shared(smc);
    const uint32_t sbX  = sb + OFF_X;
    const uint32_t sbAO = sb + OFF_AO;
    const uint32_t sbWO = sb + OFF_WO;

    // ---- stage X (96x128 fp16) + scalars ----
    {
        const float4* xg = (const float4*)(x + (size_t)cta * MR * DM);
        #pragma unroll
        for (int j = 0; j < 12; j++) {
            int i = tid + j * THREADS;              // < 3072
            int row = i >> 5, kk = (i & 31) * 4;
            *(uint2*)(Xh + row * TSTR + kk) = f4_to_h4(xg[i]);
        }
    }
    if (tid < DM) {
        bqs[tid] = bq[tid]; bks[tid] = bk[tid];
        bvs[tid] = bv[tid]; bos[tid] = bo[tid];
    }
    if (tid < NJ * NJ) adjb[tid] = adj[tid] * bias_scale[0];
    if (tid < MR)      kmsk[tid] = -10.0f * (1.0f - vis[(size_t)cta * MR + tid]);
    __syncthreads();

    // GEMM1 warp tiling: 8 warps, mg2 (48 rows) x ng4 (24 cols)
    const int mg = warp >> 2, ng = warp & 3;

    // A-fragment ldsm addresses (X)
    uint32_t aaddr[3];
    #pragma unroll
    for (int i = 0; i < 3; i++)
        aaddr[i] = sbX + (uint32_t)((mg * 48 + i * 16 + (lane & 15)) * TSTR) * 2
                       + ((lane >> 4) * 16);

    for (int h = 0; h < NH; ++h) {
        // ===== GEMM1: QKV(96x96) = X @ [Wq|Wk|Wv]_h^T, B direct from GMEM =====
        // B-fragment offsets into gWqkv (halves); tile j covers cols ng*24 + j*8
        uint32_t boff[3];
        #pragma unroll
        for (int j = 0; j < 3; j++) {
            int col0 = ng * 24 + j * 8;
            int sub = col0 >> 5;                     // 0=Wq,1=Wk,2=Wv
            int n0  = col0 & 31;
            boff[j] = (uint32_t)(sub * 16384 + (h * HD + n0 + (lane >> 2)) * DM
                                 + (lane & 3) * 2);
        }

        float acc[3][3][4];
        #pragma unroll
        for (int i = 0; i < 3; i++)
            #pragma unroll
            for (int j = 0; j < 3; j++)
                #pragma unroll
                for (int r = 0; r < 4; r++) acc[i][j][r] = 0.0f;

        uint32_t bcur[3][2], bnxt[3][2];
        #pragma unroll
        for (int j = 0; j < 3; j++) {
            bcur[j][0] = *(const uint32_t*)(gWqkv + boff[j]);
            bcur[j][1] = *(const uint32_t*)(gWqkv + boff[j] + 8);
        }
        #pragma unroll
        for (int ks = 0; ks < 8; ks++) {
            if (ks < 7) {
                #pragma unroll
                for (int j = 0; j < 3; j++) {
                    bnxt[j][0] = *(const uint32_t*)(gWqkv + boff[j] + (ks + 1) * 16);
                    bnxt[j][1] = *(const uint32_t*)(gWqkv + boff[j] + (ks + 1) * 16 + 8);
                }
            }
            uint32_t a[3][4];
            #pragma unroll
            for (int i = 0; i < 3; i++) ldsm_x4(a[i], aaddr[i] + ks * 32);
            #pragma unroll
            for (int i = 0; i < 3; i++)
                #pragma unroll
                for (int j = 0; j < 3; j++) mma16(acc[i][j], a[i], bcur[j]);
            #pragma unroll
            for (int j = 0; j < 3; j++) {
                bcur[j][0] = bnxt[j][0]; bcur[j][1] = bnxt[j][1];
            }
        }

        __syncthreads();   // previous attention finished reading QKV

        // bias + scatter to fp16 QKV
        #pragma unroll
        for (int i = 0; i < 3; i++) {
            int row = mg * 48 + i * 16 + gid;
            #pragma unroll
            for (int j = 0; j < 3; j++) {
                int col = ng * 24 + j * 8 + 2 * tig;
                float b0, b1;
                if (col < 32)      { b0 = bqs[h*HD+col];    b1 = bqs[h*HD+col+1]; }
                else if (col < 64) { b0 = bks[h*HD+col-32]; b1 = bks[h*HD+col-31]; }
                else               { b0 = bvs[h*HD+col-64]; b1 = bvs[h*HD+col-63]; }
                *(__half2*)(QKV + row * QSTR + col) =
                    __floats2half2_rn(acc[i][j][0] + b0, acc[i][j][1] + b1);
                *(__half2*)(QKV + (row + 8) * QSTR + col) =
                    __floats2half2_rn(acc[i][j][2] + b0, acc[i][j][3] + b1);
            }
        }
        __syncthreads();

        // ===== attention (tid<192, 2 threads/row) =====
        if (tid < 192) {
            int row  = tid >> 1;
            int half = tid & 1;
            int lb = row / NJ, ln = row - lb * NJ;

            float q[16];
            {
                const uint4* qp = (const uint4*)(QKV + row * QSTR + half * 16);
                uint4 u0 = qp[0], u1 = qp[1];
                const __half2* hp0 = (const __half2*)&u0;
                const __half2* hp1 = (const __half2*)&u1;
                #pragma unroll
                for (int j = 0; j < 4; j++) {
                    float2 f0 = __half22float2(hp0[j]);
                    float2 f1 = __half22float2(hp1[j]);
                    q[2*j] = f0.x; q[2*j+1] = f0.y;
                    q[8+2*j] = f1.x; q[8+2*j+1] = f1.y;
                }
            }
            float s[NJ];
            #pragma unroll
            for (int m = 0; m < NJ; m++) {
                const uint4* kp = (const uint4*)(QKV + (lb * NJ + m) * QSTR + 32 + half * 16);
                uint4 u0 = kp[0], u1 = kp[1];
                const __half2* hp0 = (const __half2*)&u0;
                const __half2* hp1 = (const __half2*)&u1;
                float dot = 0.0f;
                #pragma unroll
                for (int j = 0; j < 4; j++) {
                    float2 f0 = __half22float2(hp0[j]);
                    float2 f1 = __half22float2(hp1[j]);
                    dot += q[2*j]*f0.x + q[2*j+1]*f0.y + q[8+2*j]*f1.x + q[8+2*j+1]*f1.y;
                }
                dot += __shfl_xor_sync(0xFFFFFFFFu, dot, 1);
                s[m] = dot * 0.17677669529663687f + adjb[ln * NJ + m] + kmsk[lb * NJ + m];
            }
            float mx = s[0];
            #pragma unroll
            for (int m = 1; m < NJ; m++) mx = fmaxf(mx, s[m]);
            float sum = 0.0f;
            #pragma unroll
            for (int m = 0; m < NJ; m++) { s[m] = __expf(s[m] - mx); sum += s[m]; }
            float inv = 1.0f / sum;

            float ao[16];
            #pragma unroll
            for (int j = 0; j < 16; j++) ao[j] = 0.0f;
            #pragma unroll
            for (int m = 0; m < NJ; m++) {
                float p = s[m] * inv;
                const uint4* vp = (const uint4*)(QKV + (lb * NJ + m) * QSTR + 64 + half * 16);
                uint4 u0 = vp[0], u1 = vp[1];
                const __half2* hp0 = (const __half2*)&u0;
                const __half2* hp1 = (const __half2*)&u1;
                #pragma unroll
                for (int j = 0; j < 4; j++) {
                    float2 f0 = __half22float2(hp0[j]);
                    float2 f1 = __half22float2(hp1[j]);
                    ao[2*j]   += p * f0.x; ao[2*j+1]   += p * f0.y;
                    ao[8+2*j] += p * f1.x; ao[8+2*j+1] += p * f1.y;
                }
            }
            __half* dst = AOh + row * TSTR + h * HD + half * 16;
            #pragma unroll
            for (int j = 0; j < 4; j++)
                *(__half2*)(dst + 2*j) = __floats2half2_rn(ao[2*j], ao[2*j+1]);
            #pragma unroll
            for (int j = 0; j < 4; j++)
                *(__half2*)(dst + 8 + 2*j) = __floats2half2_rn(ao[8+2*j], ao[8+2*j+1]);
        }
        // no sync here: next head's GEMM1 touches only X (smem) + gmem; the
        // pre-scatter sync orders QKV reuse.
    }

    __syncthreads();   // attention h=3 done before Wo overlays X|QKV

    // ---- stage Wo (128x128 fp16, no conversion) into freed region ----
    #pragma unroll
    for (int j = 0; j < 8; j++) {
        int i = tid + j * THREADS;                   // < 2048 uint4
        int row = i >> 4, c = (i & 15) * 8;
        *(uint4*)(WOh + row * TSTR + c) = *(const uint4*)(gWo + row * DM + c);
    }
    __syncthreads();

    // ===== final GEMM (8 warps, mg2 x ng4): Y(96x128) = AO @ Wo^T =====
    {
        const int fmg = warp >> 2, fng = warp & 3;
        uint32_t faddr[3], baddr[2];
        #pragma unroll
        for (int i = 0; i < 3; i++)
            faddr[i] = sbAO + (uint32_t)((fmg * 48 + i * 16 + (lane & 15)) * TSTR) * 2
                            + ((lane >> 4) * 16);
        #pragma unroll
        for (int j = 0; j < 2; j++) {
            int row = fng * 32 + j * 16 + (lane & 7) + ((lane >> 4) * 8);
            baddr[j] = sbWO + (uint32_t)(row * TSTR) * 2 + (((lane >> 3) & 1) * 16);
        }

        float y[3][4][4];
        #pragma unroll
        for (int i = 0; i < 3; i++)
            #pragma unroll
            for (int j = 0; j < 4; j++)
                #pragma unroll
                for (int r = 0; r < 4; r++) y[i][j][r] = 0.0f;

        #pragma unroll
        for (int ks = 0; ks < 8; ks++) {
            uint32_t a[3][4], b[2][4];
            #pragma unroll
            for (int i = 0; i < 3; i++) ldsm_x4(a[i], faddr[i] + ks * 32);
            #pragma unroll
            for (int j = 0; j < 2; j++) ldsm_x4(b[j], baddr[j] + ks * 32);
            #pragma unroll
            for (int i = 0; i < 3; i++)
                #pragma unroll
                for (int j = 0; j < 2; j++) {
                    mma16(y[i][2*j],   a[i], b[j]);
                    mma16(y[i][2*j+1], a[i], b[j] + 2);
                }
        }

        #pragma unroll
        for (int i = 0; i < 3; i++) {
            int row = fmg * 48 + i * 16 + gid;
            #pragma unroll
            for (int j = 0; j < 4; j++) {
                int col = fng * 32 + j * 8 + 2 * tig;
                float b0 = bos[col], b1 = bos[col + 1];
                size_t base = ((size_t)cta * MR + row) * DM + col;
                *(float2*)(out + base)          = make_float2(y[i][j][0] + b0, y[i][j][1] + b1);
                *(float2*)(out + base + 8 * DM) = make_float2(y[i][j][2] + b0, y[i][j][3] + b1);
            }
        }
    }
}

extern "C" void kernel_launch(void* const* d_in, const int* in_sizes, int n_in,
                              void* d_out, int out_size) {
    const float* x   = (const float*)d_in[0];
    const float* vis = (const float*)d_in[1];
    const float* Wq  = (const float*)d_in[2];
    const float* bq  = (const float*)d_in[3];
    const float* Wk  = (const float*)d_in[4];
    const float* bk  = (const float*)d_in[5];
    const float* Wv  = (const float*)d_in[6];
    const float* bv  = (const float*)d_in[7];
    const float* Wo  = (const float*)d_in[8];
    const float* bo  = (const float*)d_in[9];
    const float* bsc = (const float*)d_in[10];
    const float* adj = (const float*)d_in[11];
    float* out = (float*)d_out;

    const int B = in_sizes[0] / (NJ * DM);      // 16384
    const int grid = B / TB;                    // 2048

    static bool attr_set = false;
    if (!attr_set) {
        cudaFuncSetAttribute(cross_joint_attn_kernel,
                             cudaFuncAttributeMaxDynamicSharedMemorySize, SMEM_BYTES);
        attr_set = true;
    }
    convert_weights<<<16, 256>>>(Wq, Wk, Wv, Wo);
    cross_joint_attn_kernel<<<grid, THREADS, SMEM_BYTES>>>(
        x, vis, bq, bk, bv, bo, bsc, adj, out);
}

// round 10
// speedup vs baseline: 1.1458x; 1.1458x over previous
#include <cuda_runtime.h>
#include <cuda_fp16.h>
#include <cstdint>

#define THREADS 384
#define TB 8
#define NJ 12
#define DM 128
#define NH 4
#define HD 32
#define MR 96              // rows per CTA = TB*NJ

#define TSTR 136           // fp16 tile stride (halves)
#define QSTR 104           // fp16 QKV stride (halves)

// smem byte offsets (identical to R7 layout)
#define OFF_X    0                         // 96 x 136 h = 26112
#define OFF_W    26112                     // 96 x 136 h = 26112
#define OFF_QKV  52224                     // 96 x 104 h = 19968
#define OFF_AO   72192                     // 96 x 136 h = 26112
#define OFF_WO   0                         // 128 x 136 h = 34816 (overlays X|W post-loop)
#define OFF_BQ   98304
#define OFF_BK   98816
#define OFF_BV   99328
#define OFF_BO   99840
#define OFF_ADJ  100352                    // 144 f32
#define OFF_KM   100928                    // 96 f32
#define SMEM_BYTES 101376

// pre-converted fp16 weights: [Wq|Wk|Wv] stacked, then Wo
__device__ __half gWqkv[3 * DM * DM];
__device__ __half gWo[DM * DM];

__device__ __forceinline__ uint2 f4_to_h4(float4 v) {
    __half2 a = __floats2half2_rn(v.x, v.y);
    __half2 b = __floats2half2_rn(v.z, v.w);
    uint2 r;
    r.x = *(uint32_t*)&a; r.y = *(uint32_t*)&b;
    return r;
}

__global__ void convert_weights(const float* __restrict__ Wq, const float* __restrict__ Wk,
                                const float* __restrict__ Wv, const float* __restrict__ Wo) {
    int i = blockIdx.x * 256 + threadIdx.x;        // 0..4095
    *(uint2*)(gWqkv + 0*16384 + i*4) = f4_to_h4(((const float4*)Wq)[i]);
    *(uint2*)(gWqkv + 1*16384 + i*4) = f4_to_h4(((const float4*)Wk)[i]);
    *(uint2*)(gWqkv + 2*16384 + i*4) = f4_to_h4(((const float4*)Wv)[i]);
    *(uint2*)(gWo + i*4)             = f4_to_h4(((const float4*)Wo)[i]);
}

__device__ __forceinline__ void ldsm_x4(uint32_t* r, uint32_t addr) {
    asm volatile("ldmatrix.sync.aligned.m8n8.x4.shared.b16 {%0,%1,%2,%3}, [%4];"
        : "=r"(r[0]), "=r"(r[1]), "=r"(r[2]), "=r"(r[3]) : "r"(addr));
}
__device__ __forceinline__ void mma16(float* d, const uint32_t* a, const uint32_t* b) {
    asm volatile(
        "mma.sync.aligned.m16n8k16.row.col.f32.f16.f16.f32 "
        "{%0,%1,%2,%3}, {%4,%5,%6,%7}, {%8,%9}, {%0,%1,%2,%3};"
        : "+f"(d[0]), "+f"(d[1]), "+f"(d[2]), "+f"(d[3])
        : "r"(a[0]), "r"(a[1]), "r"(a[2]), "r"(a[3]), "r"(b[0]), "r"(b[1]));
}

__global__ void __launch_bounds__(THREADS, 2)
cross_joint_attn_kernel(
    const float* __restrict__ x, const float* __restrict__ vis,
    const float* __restrict__ bq, const float* __restrict__ bk,
    const float* __restrict__ bv, const float* __restrict__ bo,
    const float* __restrict__ bias_scale, const float* __restrict__ adj,
    float* __restrict__ out)
{
    extern __shared__ __align__(16) char smc[];
    __half* Xh  = (__half*)(smc + OFF_X);
    __half* Wh  = (__half*)(smc + OFF_W);
    __half* QKV = (__half*)(smc + OFF_QKV);
    __half* AOh = (__half*)(smc + OFF_AO);
    __half* WOh = (__half*)(smc + OFF_WO);
    float* bqs  = (float*)(smc + OFF_BQ);
    float* bks  = (float*)(smc + OFF_BK);
    float* bvs  = (float*)(smc + OFF_BV);
    float* bos  = (float*)(smc + OFF_BO);
    float* adjb = (float*)(smc + OFF_ADJ);
    float* kmsk = (float*)(smc + OFF_KM);

    const int tid  = threadIdx.x;
    const int lane = tid & 31;
    const int warp = tid >> 5;
    const int cta  = blockIdx.x;
    const int gid  = lane >> 2;
    const int tig  = lane & 3;

    const uint32_t sb   = (uint32_t)__cvta_generic_to_shared(smc);
    const uint32_t sbX  = sb + OFF_X;
    const uint32_t sbW  = sb + OFF_W;
    const uint32_t sbAO = sb + OFF_AO;
    const uint32_t sbWO = sb + OFF_WO;

    // ---- stage X (96x128 fp16) ----
    {
        const float4* xg = (const float4*)(x + (size_t)cta * MR * DM);
        #pragma unroll
        for (int j = 0; j < 8; j++) {
            int i = tid + j * THREADS;              // < 3072
            int row = i >> 5, kk = (i & 31) * 4;
            *(uint2*)(Xh + row * TSTR + kk) = f4_to_h4(xg[i]);
        }
    }
    // ---- stage W head 0 (uint4 copies from pre-converted fp16) ----
    #pragma unroll
    for (int j = 0; j < 4; j++) {
        int i = tid + j * THREADS;                  // < 1536 uint4
        int row = i >> 4, c = (i & 15) * 8;
        int sub = row >> 5;
        *(uint4*)(Wh + row * TSTR + c) =
            *(const uint4*)(gWqkv + sub * 16384 + (row & 31) * DM + c);
    }
    if (tid < DM) {
        bqs[tid] = bq[tid]; bks[tid] = bk[tid];
        bvs[tid] = bv[tid]; bos[tid] = bo[tid];
    }
    if (tid < NJ * NJ) adjb[tid] = adj[tid] * bias_scale[0];
    if (tid < MR)      kmsk[tid] = -10.0f * (1.0f - vis[(size_t)cta * MR + tid]);
    __syncthreads();

    // GEMM1 tiling: 12 warps, mg6 (16 rows) x ng2 (48 cols)
    const int mg = warp >> 1, ng = warp & 1;
    uint32_t aaddr = sbX + (uint32_t)((mg * 16 + (lane & 15)) * TSTR) * 2
                         + ((lane >> 4) * 16);
    uint32_t baddr[3];
    #pragma unroll
    for (int j = 0; j < 3; j++) {
        int row = ng * 48 + j * 16 + (lane & 7) + ((lane >> 4) * 8);
        baddr[j] = sbW + (uint32_t)(row * TSTR) * 2 + (((lane >> 3) & 1) * 16);
    }

    // attention mapping: 4 threads per row, all 384 threads
    const int arow = tid >> 2, aq = tid & 3;
    const int alb  = arow / NJ, aln = arow - alb * NJ;

    for (int h = 0; h < NH; ++h) {
        // ===== GEMM1: QKV(96x96) = X @ [Wq|Wk|Wv]_h^T =====
        float acc[6][4];
        #pragma unroll
        for (int j = 0; j < 6; j++)
            #pragma unroll
            for (int r = 0; r < 4; r++) acc[j][r] = 0.0f;

        #pragma unroll
        for (int ks = 0; ks < 8; ks++) {
            uint32_t a[4], b[3][4];
            ldsm_x4(a, aaddr + ks * 32);
            #pragma unroll
            for (int j = 0; j < 3; j++) ldsm_x4(b[j], baddr[j] + ks * 32);
            #pragma unroll
            for (int j = 0; j < 3; j++) {
                mma16(acc[2*j],   a, b[j]);
                mma16(acc[2*j+1], a, b[j] + 2);
            }
        }

        // bias + scatter to fp16 QKV
        {
            int row = mg * 16 + gid;
            #pragma unroll
            for (int j = 0; j < 6; j++) {
                int col = ng * 48 + j * 8 + 2 * tig;
                float b0, b1;
                if (col < 32)      { b0 = bqs[h*HD+col];    b1 = bqs[h*HD+col+1]; }
                else if (col < 64) { b0 = bks[h*HD+col-32]; b1 = bks[h*HD+col-31]; }
                else               { b0 = bvs[h*HD+col-64]; b1 = bvs[h*HD+col-63]; }
                *(__half2*)(QKV + row * QSTR + col) =
                    __floats2half2_rn(acc[j][0] + b0, acc[j][1] + b1);
                *(__half2*)(QKV + (row + 8) * QSTR + col) =
                    __floats2half2_rn(acc[j][2] + b0, acc[j][3] + b1);
            }
        }
        __syncthreads();

        // ===== attention: 4 threads/row, all 384 threads =====
        {
            float q[8];
            {
                uint4 u = *(const uint4*)(QKV + arow * QSTR + aq * 8);
                const __half2* hp = (const __half2*)&u;
                #pragma unroll
                for (int j = 0; j < 4; j++) {
                    float2 f = __half22float2(hp[j]);
                    q[2*j] = f.x; q[2*j+1] = f.y;
                }
            }
            float s[NJ];
            #pragma unroll
            for (int m = 0; m < NJ; m++) {
                uint4 u = *(const uint4*)(QKV + (alb * NJ + m) * QSTR + 32 + aq * 8);
                const __half2* hp = (const __half2*)&u;
                float dot = 0.0f;
                #pragma unroll
                for (int j = 0; j < 4; j++) {
                    float2 f = __half22float2(hp[j]);
                    dot += q[2*j] * f.x + q[2*j+1] * f.y;
                }
                dot += __shfl_xor_sync(0xFFFFFFFFu, dot, 1);
                dot += __shfl_xor_sync(0xFFFFFFFFu, dot, 2);
                s[m] = dot * 0.17677669529663687f + adjb[aln * NJ + m] + kmsk[alb * NJ + m];
            }
            float mx = s[0];
            #pragma unroll
            for (int m = 1; m < NJ; m++) mx = fmaxf(mx, s[m]);
            float sum = 0.0f;
            #pragma unroll
            for (int m = 0; m < NJ; m++) { s[m] = __expf(s[m] - mx); sum += s[m]; }
            float inv = 1.0f / sum;

            float ao[8];
            #pragma unroll
            for (int j = 0; j < 8; j++) ao[j] = 0.0f;
            #pragma unroll
            for (int m = 0; m < NJ; m++) {
                float p = s[m] * inv;
                uint4 u = *(const uint4*)(QKV + (alb * NJ + m) * QSTR + 64 + aq * 8);
                const __half2* hp = (const __half2*)&u;
                #pragma unroll
                for (int j = 0; j < 4; j++) {
                    float2 f = __half22float2(hp[j]);
                    ao[2*j] += p * f.x; ao[2*j+1] += p * f.y;
                }
            }
            __half2 o0 = __floats2half2_rn(ao[0], ao[1]);
            __half2 o1 = __floats2half2_rn(ao[2], ao[3]);
            __half2 o2 = __floats2half2_rn(ao[4], ao[5]);
            __half2 o3 = __floats2half2_rn(ao[6], ao[7]);
            uint4 pack;
            pack.x = *(uint32_t*)&o0; pack.y = *(uint32_t*)&o1;
            pack.z = *(uint32_t*)&o2; pack.w = *(uint32_t*)&o3;
            *(uint4*)(AOh + arow * TSTR + h * HD + aq * 8) = pack;
        }

        // ---- stage W_{h+1} (uint4 copies) ----
        if (h < 3) {
            #pragma unroll
            for (int j = 0; j < 4; j++) {
                int i = tid + j * THREADS;          // < 1536
                int row = i >> 4, c = (i & 15) * 8;
                int sub = row >> 5;
                *(uint4*)(Wh + row * TSTR + c) =
                    *(const uint4*)(gWqkv + sub * 16384 + ((h+1) * HD + (row & 31)) * DM + c);
            }
        }
        __syncthreads();
    }

    // ---- stage Wo (fp16 uint4 copies) into freed X|W region ----
    #pragma unroll
    for (int j = 0; j < 6; j++) {
        int i = tid + j * THREADS;                  // < 2176? bound-check
        if (i < 2048) {
            int row = i >> 4, c = (i & 15) * 8;
            *(uint4*)(WOh + row * TSTR + c) = *(const uint4*)(gWo + row * DM + c);
        }
    }
    __syncthreads();

    // ===== final GEMM (12 warps, fm6 x fn2): Y(96x128) = AO @ Wo^T =====
    {
        const int fm = warp >> 1, fn = warp & 1;
        uint32_t faddr = sbAO + (uint32_t)((fm * 16 + (lane & 15)) * TSTR) * 2
                              + ((lane >> 4) * 16);
        uint32_t fbaddr[4];
        #pragma unroll
        for (int j = 0; j < 4; j++) {
            int row = fn * 64 + j * 16 + (lane & 7) + ((lane >> 4) * 8);
            fbaddr[j] = sbWO + (uint32_t)(row * TSTR) * 2 + (((lane >> 3) & 1) * 16);
        }

        float y[8][4];
        #pragma unroll
        for (int j = 0; j < 8; j++)
            #pragma unroll
            for (int r = 0; r < 4; r++) y[j][r] = 0.0f;

        #pragma unroll
        for (int ks = 0; ks < 8; ks++) {
            uint32_t a[4], b[4][4];
            ldsm_x4(a, faddr + ks * 32);
            #pragma unroll
            for (int j = 0; j < 4; j++) ldsm_x4(b[j], fbaddr[j] + ks * 32);
            #pragma unroll
            for (int j = 0; j < 4; j++) {
                mma16(y[2*j],   a, b[j]);
                mma16(y[2*j+1], a, b[j] + 2);
            }
        }

        int row = fm * 16 + gid;
        #pragma unroll
        for (int j = 0; j < 8; j++) {
            int col = fn * 64 + j * 8 + 2 * tig;
            float b0 = bos[col], b1 = bos[col + 1];
            size_t base = ((size_t)cta * MR + row) * DM + col;
            *(float2*)(out + base)          = make_float2(y[j][0] + b0, y[j][1] + b1);
            *(float2*)(out + base + 8 * DM) = make_float2(y[j][2] + b0, y[j][3] + b1);
        }
    }
}

extern "C" void kernel_launch(void* const* d_in, const int* in_sizes, int n_in,
                              void* d_out, int out_size) {
    const float* x   = (const float*)d_in[0];
    const float* vis = (const float*)d_in[1];
    const float* Wq  = (const float*)d_in[2];
    const float* bq  = (const float*)d_in[3];
    const float* Wk  = (const float*)d_in[4];
    const float* bk  = (const float*)d_in[5];
    const float* Wv  = (const float*)d_in[6];
    const float* bv  = (const float*)d_in[7];
    const float* Wo  = (const float*)d_in[8];
    const float* bo  = (const float*)d_in[9];
    const float* bsc = (const float*)d_in[10];
    const float* adj = (const float*)d_in[11];
    float* out = (float*)d_out;

    const int B = in_sizes[0] / (NJ * DM);      // 16384
    const int grid = B / TB;                    // 2048

    static bool attr_set = false;
    if (!attr_set) {
        cudaFuncSetAttribute(cross_joint_attn_kernel,
                             cudaFuncAttributeMaxDynamicSharedMemorySize, SMEM_BYTES);
        attr_set = true;
    }
    convert_weights<<<16, 256>>>(Wq, Wk, Wv, Wo);
    cross_joint_attn_kernel<<<grid, THREADS, SMEM_BYTES>>>(
        x, vis, bq, bk, bv, bo, bsc, adj, out);
}

// round 11
// speedup vs baseline: 1.4751x; 1.2874x over previous
#include <cuda_runtime.h>
#include <cuda_fp16.h>
#include <cstdint>

#define THREADS 384
#define TB 8
#define NJ 12
#define DM 128
#define NH 4
#define HD 32
#define MR 96              // valid rows per CTA
#define PBR 16             // padded rows per batch
#define PR  128            // padded QKV rows (8 batches x 16)

#define TSTR 136           // fp16 tile stride (halves) for X/W/AO/Wo
#define QSTR 104           // fp16 QKV stride (halves)

// smem byte offsets
#define OFF_X    0                          // 96 x 136 h  = 26112
#define OFF_W    26112                      // 96 x 136 h  = 26112
#define OFF_QKV  52224                      // 128 x 104 h = 26624 (batch-padded)
#define OFF_AO   78848                      // 96 x 136 h  = 26112
#define OFF_WO   0                          // 128 x 136 h = 34816 (overlays X|W)
#define OFF_BQ   104960
#define OFF_BK   105472
#define OFF_BV   105984
#define OFF_BO   106496
#define OFF_ADJ  107008                     // 144 f32
#define OFF_KM   107584                     // 96 f32
#define SMEM_BYTES 107968

// pre-converted fp16 weights
__device__ __half gWqkv[3 * DM * DM];
__device__ __half gWo[DM * DM];

__device__ __forceinline__ uint2 f4_to_h4(float4 v) {
    __half2 a = __floats2half2_rn(v.x, v.y);
    __half2 b = __floats2half2_rn(v.z, v.w);
    uint2 r;
    r.x = *(uint32_t*)&a; r.y = *(uint32_t*)&b;
    return r;
}

__global__ void convert_weights(const float* __restrict__ Wq, const float* __restrict__ Wk,
                                const float* __restrict__ Wv, const float* __restrict__ Wo) {
    int i = blockIdx.x * 256 + threadIdx.x;       // 0..4095
    *(uint2*)(gWqkv + 0*16384 + i*4) = f4_to_h4(((const float4*)Wq)[i]);
    *(uint2*)(gWqkv + 1*16384 + i*4) = f4_to_h4(((const float4*)Wk)[i]);
    *(uint2*)(gWqkv + 2*16384 + i*4) = f4_to_h4(((const float4*)Wv)[i]);
    *(uint2*)(gWo + i*4)             = f4_to_h4(((const float4*)Wo)[i]);
}

__device__ __forceinline__ void ldsm_x4(uint32_t* r, uint32_t addr) {
    asm volatile("ldmatrix.sync.aligned.m8n8.x4.shared.b16 {%0,%1,%2,%3}, [%4];"
        : "=r"(r[0]), "=r"(r[1]), "=r"(r[2]), "=r"(r[3]) : "r"(addr));
}
__device__ __forceinline__ void ldsm_x4t(uint32_t* r, uint32_t addr) {
    asm volatile("ldmatrix.sync.aligned.m8n8.x4.trans.shared.b16 {%0,%1,%2,%3}, [%4];"
        : "=r"(r[0]), "=r"(r[1]), "=r"(r[2]), "=r"(r[3]) : "r"(addr));
}
__device__ __forceinline__ void mma16(float* d, const uint32_t* a, const uint32_t* b) {
    asm volatile(
        "mma.sync.aligned.m16n8k16.row.col.f32.f16.f16.f32 "
        "{%0,%1,%2,%3}, {%4,%5,%6,%7}, {%8,%9}, {%0,%1,%2,%3};"
        : "+f"(d[0]), "+f"(d[1]), "+f"(d[2]), "+f"(d[3])
        : "r"(a[0]), "r"(a[1]), "r"(a[2]), "r"(a[3]), "r"(b[0]), "r"(b[1]));
}
__device__ __forceinline__ uint32_t h2u(__half2 h) { return *(uint32_t*)&h; }

__global__ void __launch_bounds__(THREADS, 2)
cross_joint_attn_kernel(
    const float* __restrict__ x, const float* __restrict__ vis,
    const float* __restrict__ bq, const float* __restrict__ bk,
    const float* __restrict__ bv, const float* __restrict__ bo,
    const float* __restrict__ bias_scale, const float* __restrict__ adj,
    float* __restrict__ out)
{
    extern __shared__ __align__(16) char smc[];
    __half* Xh  = (__half*)(smc + OFF_X);
    __half* Wh  = (__half*)(smc + OFF_W);
    __half* QKV = (__half*)(smc + OFF_QKV);
    __half* AOh = (__half*)(smc + OFF_AO);
    __half* WOh = (__half*)(smc + OFF_WO);
    float* bqs  = (float*)(smc + OFF_BQ);
    float* bks  = (float*)(smc + OFF_BK);
    float* bvs  = (float*)(smc + OFF_BV);
    float* bos  = (float*)(smc + OFF_BO);
    float* adjb = (float*)(smc + OFF_ADJ);
    float* kmsk = (float*)(smc + OFF_KM);

    const int tid  = threadIdx.x;
    const int lane = tid & 31;
    const int warp = tid >> 5;
    const int cta  = blockIdx.x;
    const int gid  = lane >> 2;
    const int tig  = lane & 3;

    const uint32_t sb    = (uint32_t)__cvta_generic_to_shared(smc);
    const uint32_t sbX   = sb + OFF_X;
    const uint32_t sbW   = sb + OFF_W;
    const uint32_t sbQKV = sb + OFF_QKV;
    const uint32_t sbAO  = sb + OFF_AO;
    const uint32_t sbWO  = sb + OFF_WO;

    // ---- stage X (96x128 fp16) ----
    {
        const float4* xg = (const float4*)(x + (size_t)cta * MR * DM);
        #pragma unroll
        for (int j = 0; j < 8; j++) {
            int i = tid + j * THREADS;             // < 3072
            int row = i >> 5, kk = (i & 31) * 4;
            *(uint2*)(Xh + row * TSTR + kk) = f4_to_h4(xg[i]);
        }
    }
    // ---- stage W head 0 ----
    #pragma unroll
    for (int j = 0; j < 4; j++) {
        int i = tid + j * THREADS;                 // < 1536 uint4
        int row = i >> 4, c = (i & 15) * 8;
        int sub = row >> 5;
        *(uint4*)(Wh + row * TSTR + c) =
            *(const uint4*)(gWqkv + sub * 16384 + (row & 31) * DM + c);
    }
    // ---- zero QKV pad rows (rows 12..15 per batch) ----
    {
        for (int z = tid; z < 8 * 4 * 13; z += THREADS) {
            int b = z / 52, rem = z - b * 52;
            int j = 12 + rem / 13, c16 = (rem % 13) * 8;
            *(uint4*)(QKV + (b * PBR + j) * QSTR + c16) = make_uint4(0, 0, 0, 0);
        }
    }
    if (tid < DM) {
        bqs[tid] = bq[tid]; bks[tid] = bk[tid];
        bvs[tid] = bv[tid]; bos[tid] = bo[tid];
    }
    if (tid < NJ * NJ) adjb[tid] = adj[tid] * bias_scale[0];
    if (tid < MR)      kmsk[tid] = -10.0f * (1.0f - vis[(size_t)cta * MR + tid]);
    __syncthreads();

    // GEMM1 tiling: 12 warps, mg6 (16 rows) x ng2 (48 cols)
    const int mg = warp >> 1, ng = warp & 1;
    uint32_t aaddr = sbX + (uint32_t)((mg * 16 + (lane & 15)) * TSTR) * 2
                         + ((lane >> 4) * 16);
    uint32_t baddr[3];
    #pragma unroll
    for (int j = 0; j < 3; j++) {
        int row = ng * 48 + j * 16 + (lane & 7) + ((lane >> 4) * 8);
        baddr[j] = sbW + (uint32_t)(row * TSTR) * 2 + (((lane >> 3) & 1) * 16);
    }

    const float QSCALE = 0.17677669529663687f;

    for (int h = 0; h < NH; ++h) {
        // ===== GEMM1: QKV(96x96) = X @ [Wq|Wk|Wv]_h^T =====
        float acc[6][4];
        #pragma unroll
        for (int j = 0; j < 6; j++)
            #pragma unroll
            for (int r = 0; r < 4; r++) acc[j][r] = 0.0f;

        #pragma unroll
        for (int ks = 0; ks < 8; ks++) {
            uint32_t a[4], b[3][4];
            ldsm_x4(a, aaddr + ks * 32);
            #pragma unroll
            for (int j = 0; j < 3; j++) ldsm_x4(b[j], baddr[j] + ks * 32);
            #pragma unroll
            for (int j = 0; j < 3; j++) {
                mma16(acc[2*j],   a, b[j]);
                mma16(acc[2*j+1], a, b[j] + 2);
            }
        }

        // bias (+Q prescale) + scatter to batch-padded fp16 QKV
        {
            int r0 = mg * 16 + gid;
            int pr0 = (r0 / NJ) * PBR + (r0 % NJ);
            int r1 = r0 + 8;
            int pr1 = (r1 / NJ) * PBR + (r1 % NJ);
            #pragma unroll
            for (int j = 0; j < 6; j++) {
                int col = ng * 48 + j * 8 + 2 * tig;
                float b0, b1, sc = 1.0f;
                if (col < 32)      { b0 = bqs[h*HD+col];    b1 = bqs[h*HD+col+1]; sc = QSCALE; }
                else if (col < 64) { b0 = bks[h*HD+col-32]; b1 = bks[h*HD+col-31]; }
                else               { b0 = bvs[h*HD+col-64]; b1 = bvs[h*HD+col-63]; }
                *(__half2*)(QKV + pr0 * QSTR + col) =
                    __floats2half2_rn((acc[j][0] + b0) * sc, (acc[j][1] + b1) * sc);
                *(__half2*)(QKV + pr1 * QSTR + col) =
                    __floats2half2_rn((acc[j][2] + b0) * sc, (acc[j][3] + b1) * sc);
            }
        }
        __syncthreads();

        // ===== attention via tensor cores: warp w<8 handles batch w =====
        if (warp < 8) {
            const int w = warp;
            const uint32_t bq16 = sbQKV + (uint32_t)(w * PBR * QSTR) * 2;

            // Q A-fragments (16x32): 2 k-steps
            uint32_t aQ[2][4];
            {
                uint32_t ad = bq16 + (uint32_t)((lane & 15) * QSTR) * 2 + ((lane >> 4) * 16);
                ldsm_x4(aQ[0], ad);
                ldsm_x4(aQ[1], ad + 32);
            }
            // K B-fragments: n=16 keys, 2 k-steps
            uint32_t bK[2][4];
            {
                uint32_t ad = bq16 + (uint32_t)(((lane & 7) + ((lane >> 4) * 8)) * QSTR) * 2
                            + 64 + (((lane >> 3) & 1) * 16);
                ldsm_x4(bK[0], ad);
                ldsm_x4(bK[1], ad + 32);
            }

            // S accumulators preloaded with adjacency + visibility bias
            float sacc[2][4];
            #pragma unroll
            for (int nt = 0; nt < 2; nt++) {
                int cb = nt * 8 + 2 * tig;
                int r0 = gid, r1 = gid + 8;
                float k0 = (cb < NJ)     ? kmsk[w * NJ + cb]     : 0.0f;
                float k1 = (cb + 1 < NJ) ? kmsk[w * NJ + cb + 1] : 0.0f;
                sacc[nt][0] = (r0 < NJ && cb < NJ)     ? adjb[r0 * NJ + cb] + k0     : 0.0f;
                sacc[nt][1] = (r0 < NJ && cb + 1 < NJ) ? adjb[r0 * NJ + cb + 1] + k1 : 0.0f;
                sacc[nt][2] = (r1 < NJ && cb < NJ)     ? adjb[r1 * NJ + cb] + k0     : 0.0f;
                sacc[nt][3] = (r1 < NJ && cb + 1 < NJ) ? adjb[r1 * NJ + cb + 1] + k1 : 0.0f;
            }
            #pragma unroll
            for (int ks = 0; ks < 2; ks++) {
                mma16(sacc[0], aQ[ks], bK[ks]);
                mma16(sacc[1], aQ[ks], bK[ks] + 2);
            }
            // mask invalid key columns
            #pragma unroll
            for (int nt = 0; nt < 2; nt++) {
                int cb = nt * 8 + 2 * tig;
                if (cb >= NJ)     { sacc[nt][0] = -1e30f; sacc[nt][2] = -1e30f; }
                if (cb + 1 >= NJ) { sacc[nt][1] = -1e30f; sacc[nt][3] = -1e30f; }
            }

            // softmax: row gid -> {s[0][0],s[0][1],s[1][0],s[1][1]}, row gid+8 -> {s[0][2],...}
            float m0 = fmaxf(fmaxf(sacc[0][0], sacc[0][1]), fmaxf(sacc[1][0], sacc[1][1]));
            float m1 = fmaxf(fmaxf(sacc[0][2], sacc[0][3]), fmaxf(sacc[1][2], sacc[1][3]));
            m0 = fmaxf(m0, __shfl_xor_sync(0xFFFFFFFFu, m0, 1));
            m0 = fmaxf(m0, __shfl_xor_sync(0xFFFFFFFFu, m0, 2));
            m1 = fmaxf(m1, __shfl_xor_sync(0xFFFFFFFFu, m1, 1));
            m1 = fmaxf(m1, __shfl_xor_sync(0xFFFFFFFFu, m1, 2));

            float e00 = __expf(sacc[0][0] - m0), e01 = __expf(sacc[0][1] - m0);
            float e10 = __expf(sacc[1][0] - m0), e11 = __expf(sacc[1][1] - m0);
            float f00 = __expf(sacc[0][2] - m1), f01 = __expf(sacc[0][3] - m1);
            float f10 = __expf(sacc[1][2] - m1), f11 = __expf(sacc[1][3] - m1);

            float s0 = e00 + e01 + e10 + e11;
            float s1 = f00 + f01 + f10 + f11;
            s0 += __shfl_xor_sync(0xFFFFFFFFu, s0, 1);
            s0 += __shfl_xor_sync(0xFFFFFFFFu, s0, 2);
            s1 += __shfl_xor_sync(0xFFFFFFFFu, s1, 1);
            s1 += __shfl_xor_sync(0xFFFFFFFFu, s1, 2);
            float i0 = 1.0f / s0, i1 = 1.0f / s1;

            // P A-fragments (fp16) from S fragments
            uint32_t pa[4];
            pa[0] = h2u(__floats2half2_rn(e00 * i0, e01 * i0));   // row gid,   k 2tig..
            pa[1] = h2u(__floats2half2_rn(f00 * i1, f01 * i1));   // row gid+8, k 2tig..
            pa[2] = h2u(__floats2half2_rn(e10 * i0, e11 * i0));   // row gid,   k 8+2tig..
            pa[3] = h2u(__floats2half2_rn(f10 * i1, f11 * i1));   // row gid+8, k 8+2tig..

            // V B-fragments via ldmatrix.trans: dims 0-15 and 16-31
            uint32_t vb[2][4];
            {
                uint32_t ad = bq16 + (uint32_t)((lane & 15) * QSTR) * 2
                            + 128 + ((lane >> 4) * 16);
                ldsm_x4t(vb[0], ad);
                ldsm_x4t(vb[1], ad + 32);
            }
            float oacc[4][4];
            #pragma unroll
            for (int j = 0; j < 4; j++)
                #pragma unroll
                for (int r = 0; r < 4; r++) oacc[j][r] = 0.0f;
            mma16(oacc[0], pa, vb[0]);
            mma16(oacc[1], pa, vb[0] + 2);
            mma16(oacc[2], pa, vb[1]);
            mma16(oacc[3], pa, vb[1] + 2);

            // store AO (valid rows only)
            int r0 = gid;                       // < 12 always
            __half* d0 = AOh + (w * NJ + r0) * TSTR + h * HD + 2 * tig;
            #pragma unroll
            for (int j = 0; j < 4; j++)
                *(__half2*)(d0 + j * 8) = __floats2half2_rn(oacc[j][0], oacc[j][1]);
            int r1 = gid + 8;
            if (r1 < NJ) {
                __half* d1 = AOh + (w * NJ + r1) * TSTR + h * HD + 2 * tig;
                #pragma unroll
                for (int j = 0; j < 4; j++)
                    *(__half2*)(d1 + j * 8) = __floats2half2_rn(oacc[j][2], oacc[j][3]);
            }
        } else if (h < 3) {
            // warps 8..11: stage next head's W
            int t2 = tid - 256;
            #pragma unroll
            for (int j = 0; j < 12; j++) {
                int i = t2 + j * 128;              // < 1536
                int row = i >> 4, c = (i & 15) * 8;
                int sub = row >> 5;
                *(uint4*)(Wh + row * TSTR + c) =
                    *(const uint4*)(gWqkv + sub * 16384 + ((h+1) * HD + (row & 31)) * DM + c);
            }
        }
        __syncthreads();
    }

    // ---- stage Wo into freed X|W region ----
    #pragma unroll
    for (int j = 0; j < 6; j++) {
        int i = tid + j * THREADS;
        if (i < 2048) {
            int row = i >> 4, c = (i & 15) * 8;
            *(uint4*)(WOh + row * TSTR + c) = *(const uint4*)(gWo + row * DM + c);
        }
    }
    __syncthreads();

    // ===== final GEMM (12 warps, fm6 x fn2): Y(96x128) = AO @ Wo^T =====
    {
        const int fm = warp >> 1, fn = warp & 1;
        uint32_t faddr = sbAO + (uint32_t)((fm * 16 + (lane & 15)) * TSTR) * 2
                              + ((lane >> 4) * 16);
        uint32_t fbaddr[4];
        #pragma unroll
        for (int j = 0; j < 4; j++) {
            int row = fn * 64 + j * 16 + (lane & 7) + ((lane >> 4) * 8);
            fbaddr[j] = sbWO + (uint32_t)(row * TSTR) * 2 + (((lane >> 3) & 1) * 16);
        }

        float y[8][4];
        #pragma unroll
        for (int j = 0; j < 8; j++)
            #pragma unroll
            for (int r = 0; r < 4; r++) y[j][r] = 0.0f;

        #pragma unroll
        for (int ks = 0; ks < 8; ks++) {
            uint32_t a[4], b[4][4];
            ldsm_x4(a, faddr + ks * 32);
            #pragma unroll
            for (int j = 0; j < 4; j++) ldsm_x4(b[j], fbaddr[j] + ks * 32);
            #pragma unroll
            for (int j = 0; j < 4; j++) {
                mma16(y[2*j],   a, b[j]);
                mma16(y[2*j+1], a, b[j] + 2);
            }
        }

        int row = fm * 16 + gid;
        #pragma unroll
        for (int j = 0; j < 8; j++) {
            int col = fn * 64 + j * 8 + 2 * tig;
            float b0 = bos[col], b1 = bos[col + 1];
            size_t base = ((size_t)cta * MR + row) * DM + col;
            *(float2*)(out + base)          = make_float2(y[j][0] + b0, y[j][1] + b1);
            *(float2*)(out + base + 8 * DM) = make_float2(y[j][2] + b0, y[j][3] + b1);
        }
    }
}

extern "C" void kernel_launch(void* const* d_in, const int* in_sizes, int n_in,
                              void* d_out, int out_size) {
    const float* x   = (const float*)d_in[0];
    const float* vis = (const float*)d_in[1];
    const float* Wq  = (const float*)d_in[2];
    const float* bq  = (const float*)d_in[3];
    const float* Wk  = (const float*)d_in[4];
    const float* bk  = (const float*)d_in[5];
    const float* Wv  = (const float*)d_in[6];
    const float* bv  = (const float*)d_in[7];
    const float* Wo  = (const float*)d_in[8];
    const float* bo  = (const float*)d_in[9];
    const float* bsc = (const float*)d_in[10];
    const float* adj = (const float*)d_in[11];
    float* out = (float*)d_out;

    const int B = in_sizes[0] / (NJ * DM);      // 16384
    const int grid = B / TB;                    // 2048

    static bool attr_set = false;
    if (!attr_set) {
        cudaFuncSetAttribute(cross_joint_attn_kernel,
                             cudaFuncAttributeMaxDynamicSharedMemorySize, SMEM_BYTES);
        attr_set = true;
    }
    convert_weights<<<16, 256>>>(Wq, Wk, Wv, Wo);
    cross_joint_attn_kernel<<<grid, THREADS, SMEM_BYTES>>>(
        x, vis, bq, bk, bv, bo, bsc, adj, out);
}

// round 12
// speedup vs baseline: 1.5126x; 1.0254x over previous
#include <cuda_runtime.h>
#include <cuda_fp16.h>
#include <cstdint>

#define THREADS 384
#define TB 8
#define NJ 12
#define DM 128
#define NH 4
#define HD 32
#define MR 96              // valid rows per CTA
#define PBR 16             // padded rows per batch

#define TSTR 136           // fp16 tile stride (halves) for X/W/AO/Wo
#define QSTR 200           // fp16 QKV stride (halves), 2 heads: 192 data + 8 pad

// smem byte offsets
#define OFF_X    0                          // 96 x 136 h  = 26112
#define OFF_W    26112                      // 192 x 136 h = 52224 (pass W / QKV / Wo overlay)
#define OFF_AO   78336                      // 96 x 136 h  = 26112
#define OFF_BQ   104448
#define OFF_BK   104960
#define OFF_BV   105472
#define OFF_BO   105984
#define OFF_ADJ  106496                     // 144 f32
#define OFF_KM   107072                     // 96 f32
#define SMEM_BYTES 107520

// pre-converted fp16 weights
__device__ __half gWqkv[3 * DM * DM];       // [Wq|Wk|Wv] stacked: sub*16384 + row*128 + col
__device__ __half gWo[DM * DM];

__device__ __forceinline__ uint2 f4_to_h4(float4 v) {
    __half2 a = __floats2half2_rn(v.x, v.y);
    __half2 b = __floats2half2_rn(v.z, v.w);
    uint2 r;
    r.x = *(uint32_t*)&a; r.y = *(uint32_t*)&b;
    return r;
}

__global__ void convert_weights(const float* __restrict__ Wq, const float* __restrict__ Wk,
                                const float* __restrict__ Wv, const float* __restrict__ Wo) {
    int i = blockIdx.x * 256 + threadIdx.x;        // 0..4095
    *(uint2*)(gWqkv + 0*16384 + i*4) = f4_to_h4(((const float4*)Wq)[i]);
    *(uint2*)(gWqkv + 1*16384 + i*4) = f4_to_h4(((const float4*)Wk)[i]);
    *(uint2*)(gWqkv + 2*16384 + i*4) = f4_to_h4(((const float4*)Wv)[i]);
    *(uint2*)(gWo + i*4)             = f4_to_h4(((const float4*)Wo)[i]);
}

__device__ __forceinline__ void ldsm_x4(uint32_t* r, uint32_t addr) {
    asm volatile("ldmatrix.sync.aligned.m8n8.x4.shared.b16 {%0,%1,%2,%3}, [%4];"
        : "=r"(r[0]), "=r"(r[1]), "=r"(r[2]), "=r"(r[3]) : "r"(addr));
}
__device__ __forceinline__ void ldsm_x4t(uint32_t* r, uint32_t addr) {
    asm volatile("ldmatrix.sync.aligned.m8n8.x4.trans.shared.b16 {%0,%1,%2,%3}, [%4];"
        : "=r"(r[0]), "=r"(r[1]), "=r"(r[2]), "=r"(r[3]) : "r"(addr));
}
__device__ __forceinline__ void mma16(float* d, const uint32_t* a, const uint32_t* b) {
    asm volatile(
        "mma.sync.aligned.m16n8k16.row.col.f32.f16.f16.f32 "
        "{%0,%1,%2,%3}, {%4,%5,%6,%7}, {%8,%9}, {%0,%1,%2,%3};"
        : "+f"(d[0]), "+f"(d[1]), "+f"(d[2]), "+f"(d[3])
        : "r"(a[0]), "r"(a[1]), "r"(a[2]), "r"(a[3]), "r"(b[0]), "r"(b[1]));
}
__device__ __forceinline__ uint32_t h2u(__half2 h) { return *(uint32_t*)&h; }

__global__ void __launch_bounds__(THREADS, 2)
cross_joint_attn_kernel(
    const float* __restrict__ x, const float* __restrict__ vis,
    const float* __restrict__ bq, const float* __restrict__ bk,
    const float* __restrict__ bv, const float* __restrict__ bo,
    const float* __restrict__ bias_scale, const float* __restrict__ adj,
    float* __restrict__ out)
{
    extern __shared__ __align__(16) char smc[];
    __half* Xh  = (__half*)(smc + OFF_X);
    __half* Wh  = (__half*)(smc + OFF_W);
    __half* QKV = (__half*)(smc + OFF_W);     // overlay
    __half* AOh = (__half*)(smc + OFF_AO);
    float* bqs  = (float*)(smc + OFF_BQ);
    float* bks  = (float*)(smc + OFF_BK);
    float* bvs  = (float*)(smc + OFF_BV);
    float* bos  = (float*)(smc + OFF_BO);
    float* adjb = (float*)(smc + OFF_ADJ);
    float* kmsk = (float*)(smc + OFF_KM);

    const int tid  = threadIdx.x;
    const int lane = tid & 31;
    const int warp = tid >> 5;
    const int cta  = blockIdx.x;
    const int gid  = lane >> 2;
    const int tig  = lane & 3;

    const uint32_t sb    = (uint32_t)__cvta_generic_to_shared(smc);
    const uint32_t sbX   = sb + OFF_X;
    const uint32_t sbW   = sb + OFF_W;
    const uint32_t sbQKV = sb + OFF_W;
    const uint32_t sbAO  = sb + OFF_AO;

    // ---- stage X (96x128 fp16) ----
    {
        const float4* xg = (const float4*)(x + (size_t)cta * MR * DM);
        #pragma unroll
        for (int j = 0; j < 8; j++) {
            int i = tid + j * THREADS;             // < 3072
            int row = i >> 5, kk = (i & 31) * 4;
            *(uint2*)(Xh + row * TSTR + kk) = f4_to_h4(xg[i]);
        }
    }
    // ---- stage W pass 0 (heads 0,1): 192 rows x 128 ----
    #pragma unroll
    for (int j = 0; j < 8; j++) {
        int i = tid + j * THREADS;                 // < 3072 uint4
        int row = i >> 4, c = (i & 15) * 8;
        int hh  = row >= 96;
        int sub = (row - hh * 96) >> 5;            // 0=Wq 1=Wk 2=Wv
        *(uint4*)(Wh + row * TSTR + c) =
            *(const uint4*)(gWqkv + sub * 16384 + (hh * HD + (row & 31)) * DM + c);
    }
    if (tid < DM) {
        bqs[tid] = bq[tid]; bks[tid] = bk[tid];
        bvs[tid] = bv[tid]; bos[tid] = bo[tid];
    }
    if (tid < NJ * NJ) adjb[tid] = adj[tid] * bias_scale[0];
    if (tid < MR)      kmsk[tid] = -10.0f * (1.0f - vis[(size_t)cta * MR + tid]);
    __syncthreads();

    // GEMM1 tiling: 12 warps, mg2 (48 rows) x ng6 (32 cols)
    const int mg = warp / 6, ng = warp - mg * 6;
    uint32_t aaddr[3], baddr[2];
    #pragma unroll
    for (int i = 0; i < 3; i++)
        aaddr[i] = sbX + (uint32_t)((mg * 48 + i * 16 + (lane & 15)) * TSTR) * 2
                       + ((lane >> 4) * 16);
    #pragma unroll
    for (int j = 0; j < 2; j++)
        baddr[j] = sbW + (uint32_t)((ng * 32 + j * 16 + (lane & 7) + ((lane >> 4) * 8)) * TSTR) * 2
                       + (((lane >> 3) & 1) * 16);

    const float QSCALE = 0.17677669529663687f;

    for (int p = 0; p < 2; ++p) {
        // ===== GEMM1: QKV(96x192) = X @ [Wq|Wk|Wv]_{2p,2p+1}^T =====
        float acc[3][4][4];
        #pragma unroll
        for (int i = 0; i < 3; i++)
            #pragma unroll
            for (int j = 0; j < 4; j++)
                #pragma unroll
                for (int r = 0; r < 4; r++) acc[i][j][r] = 0.0f;

        #pragma unroll
        for (int ks = 0; ks < 8; ks++) {
            uint32_t a[3][4], b[2][4];
            #pragma unroll
            for (int i = 0; i < 3; i++) ldsm_x4(a[i], aaddr[i] + ks * 32);
            #pragma unroll
            for (int j = 0; j < 2; j++) ldsm_x4(b[j], baddr[j] + ks * 32);
            #pragma unroll
            for (int i = 0; i < 3; i++)
                #pragma unroll
                for (int j = 0; j < 2; j++) {
                    mma16(acc[i][2*j],   a[i], b[j]);
                    mma16(acc[i][2*j+1], a[i], b[j] + 2);
                }
        }
        __syncthreads();   // all W reads done before QKV overlay writes

        // bias (+Q prescale) + scatter to batch-padded fp16 QKV (overlay on W)
        #pragma unroll
        for (int i = 0; i < 3; i++) {
            int r0 = mg * 48 + i * 16 + gid;
            int pr0 = (r0 / NJ) * PBR + (r0 % NJ);
            int r1 = r0 + 8;
            int pr1 = (r1 / NJ) * PBR + (r1 % NJ);
            #pragma unroll
            for (int j = 0; j < 4; j++) {
                int c  = ng * 32 + (j >> 1) * 16 + (j & 1) * 8 + 2 * tig;  // 0..191
                int hh = c >= 96;
                int rr = c - hh * 96;
                int h  = 2 * p + hh;
                float b0, b1, sc = 1.0f;
                if (rr < 32)      { b0 = bqs[h*HD+rr];    b1 = bqs[h*HD+rr+1]; sc = QSCALE; }
                else if (rr < 64) { b0 = bks[h*HD+rr-32]; b1 = bks[h*HD+rr-31]; }
                else              { b0 = bvs[h*HD+rr-64]; b1 = bvs[h*HD+rr-63]; }
                *(__half2*)(QKV + pr0 * QSTR + c) =
                    __floats2half2_rn((acc[i][j][0] + b0) * sc, (acc[i][j][1] + b1) * sc);
                *(__half2*)(QKV + pr1 * QSTR + c) =
                    __floats2half2_rn((acc[i][j][2] + b0) * sc, (acc[i][j][3] + b1) * sc);
            }
        }
        __syncthreads();

        // ===== attention (warps 0..7, batch = warp), both heads of pass =====
        if (warp < 8) {
            const int w = warp;
            const uint32_t bbase = sbQKV + (uint32_t)(w * PBR * QSTR) * 2;

            // bias fragments (same for both heads)
            float bias[2][4];
            #pragma unroll
            for (int nt = 0; nt < 2; nt++) {
                int cb = nt * 8 + 2 * tig;
                int r0 = gid, r1 = gid + 8;
                float k0 = (cb < NJ)     ? kmsk[w * NJ + cb]     : 0.0f;
                float k1 = (cb + 1 < NJ) ? kmsk[w * NJ + cb + 1] : 0.0f;
                bias[nt][0] = (r0 < NJ && cb < NJ)     ? adjb[r0 * NJ + cb] + k0     : 0.0f;
                bias[nt][1] = (r0 < NJ && cb + 1 < NJ) ? adjb[r0 * NJ + cb + 1] + k1 : 0.0f;
                bias[nt][2] = (r1 < NJ && cb < NJ)     ? adjb[r1 * NJ + cb] + k0     : 0.0f;
                bias[nt][3] = (r1 < NJ && cb + 1 < NJ) ? adjb[r1 * NJ + cb + 1] + k1 : 0.0f;
            }

            #pragma unroll
            for (int hh = 0; hh < 2; hh++) {
                const uint32_t hb = bbase + hh * 192;   // 96 halves = 192 bytes

                uint32_t aQ[2][4];
                {
                    uint32_t ad = hb + (uint32_t)((lane & 15) * QSTR) * 2 + ((lane >> 4) * 16);
                    ldsm_x4(aQ[0], ad);
                    ldsm_x4(aQ[1], ad + 32);
                }
                uint32_t bK[2][4];
                {
                    uint32_t ad = hb + (uint32_t)(((lane & 7) + ((lane >> 4) * 8)) * QSTR) * 2
                                + 64 + (((lane >> 3) & 1) * 16);
                    ldsm_x4(bK[0], ad);
                    ldsm_x4(bK[1], ad + 32);
                }

                float sacc[2][4];
                #pragma unroll
                for (int nt = 0; nt < 2; nt++)
                    #pragma unroll
                    for (int r = 0; r < 4; r++) sacc[nt][r] = bias[nt][r];
                #pragma unroll
                for (int ks = 0; ks < 2; ks++) {
                    mma16(sacc[0], aQ[ks], bK[ks]);
                    mma16(sacc[1], aQ[ks], bK[ks] + 2);
                }
                #pragma unroll
                for (int nt = 0; nt < 2; nt++) {
                    int cb = nt * 8 + 2 * tig;
                    if (cb >= NJ)     { sacc[nt][0] = -1e30f; sacc[nt][2] = -1e30f; }
                    if (cb + 1 >= NJ) { sacc[nt][1] = -1e30f; sacc[nt][3] = -1e30f; }
                }

                float m0 = fmaxf(fmaxf(sacc[0][0], sacc[0][1]), fmaxf(sacc[1][0], sacc[1][1]));
                float m1 = fmaxf(fmaxf(sacc[0][2], sacc[0][3]), fmaxf(sacc[1][2], sacc[1][3]));
                m0 = fmaxf(m0, __shfl_xor_sync(0xFFFFFFFFu, m0, 1));
                m0 = fmaxf(m0, __shfl_xor_sync(0xFFFFFFFFu, m0, 2));
                m1 = fmaxf(m1, __shfl_xor_sync(0xFFFFFFFFu, m1, 1));
                m1 = fmaxf(m1, __shfl_xor_sync(0xFFFFFFFFu, m1, 2));

                float e00 = __expf(sacc[0][0] - m0), e01 = __expf(sacc[0][1] - m0);
                float e10 = __expf(sacc[1][0] - m0), e11 = __expf(sacc[1][1] - m0);
                float f00 = __expf(sacc[0][2] - m1), f01 = __expf(sacc[0][3] - m1);
                float f10 = __expf(sacc[1][2] - m1), f11 = __expf(sacc[1][3] - m1);

                float s0 = e00 + e01 + e10 + e11;
                float s1 = f00 + f01 + f10 + f11;
                s0 += __shfl_xor_sync(0xFFFFFFFFu, s0, 1);
                s0 += __shfl_xor_sync(0xFFFFFFFFu, s0, 2);
                s1 += __shfl_xor_sync(0xFFFFFFFFu, s1, 1);
                s1 += __shfl_xor_sync(0xFFFFFFFFu, s1, 2);
                float i0 = 1.0f / s0, i1 = 1.0f / s1;

                uint32_t pa[4];
                pa[0] = h2u(__floats2half2_rn(e00 * i0, e01 * i0));
                pa[1] = h2u(__floats2half2_rn(f00 * i1, f01 * i1));
                pa[2] = h2u(__floats2half2_rn(e10 * i0, e11 * i0));
                pa[3] = h2u(__floats2half2_rn(f10 * i1, f11 * i1));

                uint32_t vb[2][4];
                {
                    uint32_t ad = hb + (uint32_t)((lane & 15) * QSTR) * 2
                                + 128 + ((lane >> 4) * 16);
                    ldsm_x4t(vb[0], ad);
                    ldsm_x4t(vb[1], ad + 32);
                }
                float oacc[4][4];
                #pragma unroll
                for (int j = 0; j < 4; j++)
                    #pragma unroll
                    for (int r = 0; r < 4; r++) oacc[j][r] = 0.0f;
                mma16(oacc[0], pa, vb[0]);
                mma16(oacc[1], pa, vb[0] + 2);
                mma16(oacc[2], pa, vb[1]);
                mma16(oacc[3], pa, vb[1] + 2);

                int hcol = (2 * p + hh) * HD;
                __half* d0 = AOh + (w * NJ + gid) * TSTR + hcol + 2 * tig;
                #pragma unroll
                for (int j = 0; j < 4; j++)
                    *(__half2*)(d0 + j * 8) = __floats2half2_rn(oacc[j][0], oacc[j][1]);
                int r1 = gid + 8;
                if (r1 < NJ) {
                    __half* d1 = AOh + (w * NJ + r1) * TSTR + hcol + 2 * tig;
                    #pragma unroll
                    for (int j = 0; j < 4; j++)
                        *(__half2*)(d1 + j * 8) = __floats2half2_rn(oacc[j][2], oacc[j][3]);
                }
            }
        }
        __syncthreads();   // QKV reads done before region is re-staged

        // ---- stage next content of the W region ----
        if (p == 0) {
            // W pass 1 (heads 2,3)
            #pragma unroll
            for (int j = 0; j < 8; j++) {
                int i = tid + j * THREADS;             // < 3072
                int row = i >> 4, c = (i & 15) * 8;
                int hh  = row >= 96;
                int sub = (row - hh * 96) >> 5;
                *(uint4*)(Wh + row * TSTR + c) =
                    *(const uint4*)(gWqkv + sub * 16384 + ((2 + hh) * HD + (row & 31)) * DM + c);
            }
        } else {
            // Wo for the final GEMM
            #pragma unroll
            for (int j = 0; j < 6; j++) {
                int i = tid + j * THREADS;
                if (i < 2048) {
                    int row = i >> 4, c = (i & 15) * 8;
                    *(uint4*)(Wh + row * TSTR + c) = *(const uint4*)(gWo + row * DM + c);
                }
            }
        }
        __syncthreads();
    }

    // ===== final GEMM (12 warps, fm6 x fn2): Y(96x128) = AO @ Wo^T =====
    {
        const int fm = warp >> 1, fn = warp & 1;
        uint32_t faddr = sbAO + (uint32_t)((fm * 16 + (lane & 15)) * TSTR) * 2
                              + ((lane >> 4) * 16);
        uint32_t fbaddr[4];
        #pragma unroll
        for (int j = 0; j < 4; j++) {
            int row = fn * 64 + j * 16 + (lane & 7) + ((lane >> 4) * 8);
            fbaddr[j] = sbW + (uint32_t)(row * TSTR) * 2 + (((lane >> 3) & 1) * 16);
        }

        float y[8][4];
        #pragma unroll
        for (int j = 0; j < 8; j++)
            #pragma unroll
            for (int r = 0; r < 4; r++) y[j][r] = 0.0f;

        #pragma unroll
        for (int ks = 0; ks < 8; ks++) {
            uint32_t a[4], b[4][4];
            ldsm_x4(a, faddr + ks * 32);
            #pragma unroll
            for (int j = 0; j < 4; j++) ldsm_x4(b[j], fbaddr[j] + ks * 32);
            #pragma unroll
            for (int j = 0; j < 4; j++) {
                mma16(y[2*j],   a, b[j]);
                mma16(y[2*j+1], a, b[j] + 2);
            }
        }

        int row = fm * 16 + gid;
        #pragma unroll
        for (int j = 0; j < 8; j++) {
            int col = fn * 64 + j * 8 + 2 * tig;
            float b0 = bos[col], b1 = bos[col + 1];
            size_t base = ((size_t)cta * MR + row) * DM + col;
            *(float2*)(out + base)          = make_float2(y[j][0] + b0, y[j][1] + b1);
            *(float2*)(out + base + 8 * DM) = make_float2(y[j][2] + b0, y[j][3] + b1);
        }
    }
}

extern "C" void kernel_launch(void* const* d_in, const int* in_sizes, int n_in,
                              void* d_out, int out_size) {
    const float* x   = (const float*)d_in[0];
    const float* vis = (const float*)d_in[1];
    const float* Wq  = (const float*)d_in[2];
    const float* bq  = (const float*)d_in[3];
    const float* Wk  = (const float*)d_in[4];
    const float* bk  = (const float*)d_in[5];
    const float* Wv  = (const float*)d_in[6];
    const float* bv  = (const float*)d_in[7];
    const float* Wo  = (const float*)d_in[8];
    const float* bo  = (const float*)d_in[9];
    const float* bsc = (const float*)d_in[10];
    const float* adj = (const float*)d_in[11];
    float* out = (float*)d_out;

    const int B = in_sizes[0] / (NJ * DM);      // 16384
    const int grid = B / TB;                    // 2048

    static bool attr_set = false;
    if (!attr_set) {
        cudaFuncSetAttribute(cross_joint_attn_kernel,
                             cudaFuncAttributeMaxDynamicSharedMemorySize, SMEM_BYTES);
        attr_set = true;
    }
    convert_weights<<<16, 256>>>(Wq, Wk, Wv, Wo);
    cross_joint_attn_kernel<<<grid, THREADS, SMEM_BYTES>>>(
        x, vis, bq, bk, bv, bo, bsc, adj, out);
}

// round 14
// speedup vs baseline: 1.6751x; 1.1074x over previous
#include <cuda_runtime.h>
#include <cuda_fp16.h>
#include <cstdint>

#define THREADS 384
#define TB 8
#define NJ 12
#define DM 128
#define NH 4
#define HD 32
#define MR 96              // valid rows per CTA
#define PBR 16             // padded rows per batch

#define TSTR 136           // fp16 tile stride (halves)
#define QSTR 200           // fp16 QKV stride (halves), 2 heads

// smem byte offsets
#define OFF_X    0                          // 96 x 136 h  = 26112 (X, later Wo rows 0..95)
#define OFF_W    26112                      // 192 x 136 h = 52224 (W pass / QKV overlay / Wo rows 96..127)
#define OFF_AO   78336                      // 96 x 136 h  = 26112
#define OFF_BQ   104448
#define OFF_BK   104960
#define OFF_BV   105472
#define OFF_BO   105984
#define OFF_ADJ  106496                     // 144 f32
#define OFF_KM   107072                     // 96 f32
#define SMEM_BYTES 107520

// pre-converted fp16 weights
__device__ __half gWqkv[3 * DM * DM];       // [Wq|Wk|Wv] stacked: sub*16384 + row*128 + col
__device__ __half gWo[DM * DM];

__device__ __forceinline__ uint2 f4_to_h4(float4 v) {
    __half2 a = __floats2half2_rn(v.x, v.y);
    __half2 b = __floats2half2_rn(v.z, v.w);
    uint2 r;
    r.x = *(uint32_t*)&a; r.y = *(uint32_t*)&b;
    return r;
}

__global__ void convert_weights(const float* __restrict__ Wq, const float* __restrict__ Wk,
                                const float* __restrict__ Wv, const float* __restrict__ Wo) {
    int i = blockIdx.x * 256 + threadIdx.x;        // 0..4095
    *(uint2*)(gWqkv + 0*16384 + i*4) = f4_to_h4(((const float4*)Wq)[i]);
    *(uint2*)(gWqkv + 1*16384 + i*4) = f4_to_h4(((const float4*)Wk)[i]);
    *(uint2*)(gWqkv + 2*16384 + i*4) = f4_to_h4(((const float4*)Wv)[i]);
    *(uint2*)(gWo + i*4)             = f4_to_h4(((const float4*)Wo)[i]);
}

__device__ __forceinline__ void ldsm_x4(uint32_t* r, uint32_t addr) {
    asm volatile("ldmatrix.sync.aligned.m8n8.x4.shared.b16 {%0,%1,%2,%3}, [%4];"
        : "=r"(r[0]), "=r"(r[1]), "=r"(r[2]), "=r"(r[3]) : "r"(addr));
}
__device__ __forceinline__ void ldsm_x4t(uint32_t* r, uint32_t addr) {
    asm volatile("ldmatrix.sync.aligned.m8n8.x4.trans.shared.b16 {%0,%1,%2,%3}, [%4];"
        : "=r"(r[0]), "=r"(r[1]), "=r"(r[2]), "=r"(r[3]) : "r"(addr));
}
__device__ __forceinline__ void mma16(float* d, const uint32_t* a, const uint32_t* b) {
    asm volatile(
        "mma.sync.aligned.m16n8k16.row.col.f32.f16.f16.f32 "
        "{%0,%1,%2,%3}, {%4,%5,%6,%7}, {%8,%9}, {%0,%1,%2,%3};"
        : "+f"(d[0]), "+f"(d[1]), "+f"(d[2]), "+f"(d[3])
        : "r"(a[0]), "r"(a[1]), "r"(a[2]), "r"(a[3]), "r"(b[0]), "r"(b[1]));
}
__device__ __forceinline__ uint32_t h2u(__half2 h) { return *(uint32_t*)&h; }

__device__ __forceinline__ void cpa16(uint32_t saddr, const void* gptr) {
    asm volatile("cp.async.cg.shared.global [%0], [%1], 16;"
        :: "r"(saddr), "l"(__cvta_generic_to_global(gptr)) : "memory");
}
__device__ __forceinline__ void cp_commit() {
    asm volatile("cp.async.commit_group;" ::: "memory");
}
__device__ __forceinline__ void cp_wait0() {
    asm volatile("cp.async.wait_group 0;" ::: "memory");
}

__global__ void __launch_bounds__(THREADS, 2)
cross_joint_attn_kernel(
    const float* __restrict__ x, const float* __restrict__ vis,
    const float* __restrict__ bq, const float* __restrict__ bk,
    const float* __restrict__ bv, const float* __restrict__ bo,
    const float* __restrict__ bias_scale, const float* __restrict__ adj,
    float* __restrict__ out)
{
    extern __shared__ __align__(16) char smc[];
    __half* Xh  = (__half*)(smc + OFF_X);
    __half* QKV = (__half*)(smc + OFF_W);     // overlay on W
    __half* AOh = (__half*)(smc + OFF_AO);
    float* bqs  = (float*)(smc + OFF_BQ);
    float* bks  = (float*)(smc + OFF_BK);
    float* bvs  = (float*)(smc + OFF_BV);
    float* bos  = (float*)(smc + OFF_BO);
    float* adjb = (float*)(smc + OFF_ADJ);
    float* kmsk = (float*)(smc + OFF_KM);

    const int tid  = threadIdx.x;
    const int lane = tid & 31;
    const int warp = tid >> 5;
    const int cta  = blockIdx.x;
    const int gid  = lane >> 2;
    const int tig  = lane & 3;

    const uint32_t sb    = (uint32_t)__cvta_generic_to_shared(smc);
    const uint32_t sbX   = sb + OFF_X;
    const uint32_t sbW   = sb + OFF_W;
    const uint32_t sbQKV = sb + OFF_W;
    const uint32_t sbAO  = sb + OFF_AO;

    // ---- stage W pass 0 (heads 0,1) via cp.async, then X (fp32->fp16) ----
    #pragma unroll
    for (int j = 0; j < 8; j++) {
        int i = tid + j * THREADS;                 // < 3072 uint4
        int row = i >> 4, c = (i & 15) * 8;
        int hh  = row >= 96;
        int sub = (row - hh * 96) >> 5;            // 0=Wq 1=Wk 2=Wv
        cpa16(sbW + (uint32_t)(row * TSTR) * 2 + c * 2,
              gWqkv + sub * 16384 + (hh * HD + (row & 31)) * DM + c);
    }
    cp_commit();
    {
        const float4* xg = (const float4*)(x + (size_t)cta * MR * DM);
        #pragma unroll
        for (int j = 0; j < 8; j++) {
            int i = tid + j * THREADS;             // < 3072
            int row = i >> 5, kk = (i & 31) * 4;
            *(uint2*)(Xh + row * TSTR + kk) = f4_to_h4(xg[i]);
        }
    }
    if (tid < DM) {
        bqs[tid] = bq[tid]; bks[tid] = bk[tid];
        bvs[tid] = bv[tid]; bos[tid] = bo[tid];
    }
    if (tid < NJ * NJ) adjb[tid] = adj[tid] * bias_scale[0];
    if (tid < MR)      kmsk[tid] = -10.0f * (1.0f - vis[(size_t)cta * MR + tid]);
    cp_wait0();
    __syncthreads();

    // GEMM1 tiling: 12 warps, mg2 (48 rows) x ng6 (32 cols)
    const int mg = warp / 6, ng = warp - mg * 6;
    uint32_t aaddr[3], baddr[2];
    #pragma unroll
    for (int i = 0; i < 3; i++)
        aaddr[i] = sbX + (uint32_t)((mg * 48 + i * 16 + (lane & 15)) * TSTR) * 2
                       + ((lane >> 4) * 16);
    #pragma unroll
    for (int j = 0; j < 2; j++)
        baddr[j] = sbW + (uint32_t)((ng * 32 + j * 16 + (lane & 7) + ((lane >> 4) * 8)) * TSTR) * 2
                       + (((lane >> 3) & 1) * 16);

    const float QSCALE = 0.17677669529663687f;

    for (int p = 0; p < 2; ++p) {
        // ===== GEMM1: QKV(96x192) = X @ [Wq|Wk|Wv]_{2p,2p+1}^T =====
        float acc[3][4][4];
        #pragma unroll
        for (int i = 0; i < 3; i++)
            #pragma unroll
            for (int j = 0; j < 4; j++)
                #pragma unroll
                for (int r = 0; r < 4; r++) acc[i][j][r] = 0.0f;

        #pragma unroll
        for (int ks = 0; ks < 8; ks++) {
            uint32_t a[3][4], b[2][4];
            #pragma unroll
            for (int i = 0; i < 3; i++) ldsm_x4(a[i], aaddr[i] + ks * 32);
            #pragma unroll
            for (int j = 0; j < 2; j++) ldsm_x4(b[j], baddr[j] + ks * 32);
            #pragma unroll
            for (int i = 0; i < 3; i++)
                #pragma unroll
                for (int j = 0; j < 2; j++) {
                    mma16(acc[i][2*j],   a[i], b[j]);
                    mma16(acc[i][2*j+1], a[i], b[j] + 2);
                }
        }
        __syncthreads();   // all W (and X, for p=1) reads done before overlay writes

        // bias (+Q prescale) + scatter to batch-padded fp16 QKV (overlay on W)
        #pragma unroll
        for (int i = 0; i < 3; i++) {
            int r0 = mg * 48 + i * 16 + gid;
            int pr0 = (r0 / NJ) * PBR + (r0 % NJ);
            int r1 = r0 + 8;
            int pr1 = (r1 / NJ) * PBR + (r1 % NJ);
            #pragma unroll
            for (int j = 0; j < 4; j++) {
                int c  = ng * 32 + (j >> 1) * 16 + (j & 1) * 8 + 2 * tig;  // 0..191
                int hh = c >= 96;
                int rr = c - hh * 96;
                int h  = 2 * p + hh;
                float b0, b1, sc = 1.0f;
                if (rr < 32)      { b0 = bqs[h*HD+rr];    b1 = bqs[h*HD+rr+1]; sc = QSCALE; }
                else if (rr < 64) { b0 = bks[h*HD+rr-32]; b1 = bks[h*HD+rr-31]; }
                else              { b0 = bvs[h*HD+rr-64]; b1 = bvs[h*HD+rr-63]; }
                *(__half2*)(QKV + pr0 * QSTR + c) =
                    __floats2half2_rn((acc[i][j][0] + b0) * sc, (acc[i][j][1] + b1) * sc);
                *(__half2*)(QKV + pr1 * QSTR + c) =
                    __floats2half2_rn((acc[i][j][2] + b0) * sc, (acc[i][j][3] + b1) * sc);
            }
        }
        __syncthreads();

        // ===== attention (warps 0..7) || p==1: warps 8..11 stage Wo[0..95] -> X region =====
        if (warp < 8) {
            const int w = warp;
            const uint32_t bbase = sbQKV + (uint32_t)(w * PBR * QSTR) * 2;

            float bias[2][4];
            #pragma unroll
            for (int nt = 0; nt < 2; nt++) {
                int cb = nt * 8 + 2 * tig;
                int r0 = gid, r1 = gid + 8;
                float k0 = (cb < NJ)     ? kmsk[w * NJ + cb]     : 0.0f;
                float k1 = (cb + 1 < NJ) ? kmsk[w * NJ + cb + 1] : 0.0f;
                bias[nt][0] = (r0 < NJ && cb < NJ)     ? adjb[r0 * NJ + cb] + k0     : 0.0f;
                bias[nt][1] = (r0 < NJ && cb + 1 < NJ) ? adjb[r0 * NJ + cb + 1] + k1 : 0.0f;
                bias[nt][2] = (r1 < NJ && cb < NJ)     ? adjb[r1 * NJ + cb] + k0     : 0.0f;
                bias[nt][3] = (r1 < NJ && cb + 1 < NJ) ? adjb[r1 * NJ + cb + 1] + k1 : 0.0f;
            }

            #pragma unroll
            for (int hh = 0; hh < 2; hh++) {
                const uint32_t hb = bbase + hh * 192;

                uint32_t aQ[2][4];
                {
                    uint32_t ad = hb + (uint32_t)((lane & 15) * QSTR) * 2 + ((lane >> 4) * 16);
                    ldsm_x4(aQ[0], ad);
                    ldsm_x4(aQ[1], ad + 32);
                }
                uint32_t bK[2][4];
                {
                    uint32_t ad = hb + (uint32_t)(((lane & 7) + ((lane >> 4) * 8)) * QSTR) * 2
                                + 64 + (((lane >> 3) & 1) * 16);
                    ldsm_x4(bK[0], ad);
                    ldsm_x4(bK[1], ad + 32);
                }

                float sacc[2][4];
                #pragma unroll
                for (int nt = 0; nt < 2; nt++)
                    #pragma unroll
                    for (int r = 0; r < 4; r++) sacc[nt][r] = bias[nt][r];
                #pragma unroll
                for (int ks = 0; ks < 2; ks++) {
                    mma16(sacc[0], aQ[ks], bK[ks]);
                    mma16(sacc[1], aQ[ks], bK[ks] + 2);
                }
                #pragma unroll
                for (int nt = 0; nt < 2; nt++) {
                    int cb = nt * 8 + 2 * tig;
                    if (cb >= NJ)     { sacc[nt][0] = -1e30f; sacc[nt][2] = -1e30f; }
                    if (cb + 1 >= NJ) { sacc[nt][1] = -1e30f; sacc[nt][3] = -1e30f; }
                }

                float m0 = fmaxf(fmaxf(sacc[0][0], sacc[0][1]), fmaxf(sacc[1][0], sacc[1][1]));
                float m1 = fmaxf(fmaxf(sacc[0][2], sacc[0][3]), fmaxf(sacc[1][2], sacc[1][3]));
                m0 = fmaxf(m0, __shfl_xor_sync(0xFFFFFFFFu, m0, 1));
                m0 = fmaxf(m0, __shfl_xor_sync(0xFFFFFFFFu, m0, 2));
                m1 = fmaxf(m1, __shfl_xor_sync(0xFFFFFFFFu, m1, 1));
                m1 = fmaxf(m1, __shfl_xor_sync(0xFFFFFFFFu, m1, 2));

                float e00 = __expf(sacc[0][0] - m0), e01 = __expf(sacc[0][1] - m0);
                float e10 = __expf(sacc[1][0] - m0), e11 = __expf(sacc[1][1] - m0);
                float f00 = __expf(sacc[0][2] - m1), f01 = __expf(sacc[0][3] - m1);
                float f10 = __expf(sacc[1][2] - m1), f11 = __expf(sacc[1][3] - m1);

                float s0 = e00 + e01 + e10 + e11;
                float s1 = f00 + f01 + f10 + f11;
                s0 += __shfl_xor_sync(0xFFFFFFFFu, s0, 1);
                s0 += __shfl_xor_sync(0xFFFFFFFFu, s0, 2);
                s1 += __shfl_xor_sync(0xFFFFFFFFu, s1, 1);
                s1 += __shfl_xor_sync(0xFFFFFFFFu, s1, 2);
                float i0 = 1.0f / s0, i1 = 1.0f / s1;

                uint32_t pa[4];
                pa[0] = h2u(__floats2half2_rn(e00 * i0, e01 * i0));
                pa[1] = h2u(__floats2half2_rn(f00 * i1, f01 * i1));
                pa[2] = h2u(__floats2half2_rn(e10 * i0, e11 * i0));
                pa[3] = h2u(__floats2half2_rn(f10 * i1, f11 * i1));

                uint32_t vb[2][4];
                {
                    uint32_t ad = hb + (uint32_t)((lane & 15) * QSTR) * 2
                                + 128 + ((lane >> 4) * 16);
                    ldsm_x4t(vb[0], ad);
                    ldsm_x4t(vb[1], ad + 32);
                }
                float oacc[4][4];
                #pragma unroll
                for (int j = 0; j < 4; j++)
                    #pragma unroll
                    for (int r = 0; r < 4; r++) oacc[j][r] = 0.0f;
                mma16(oacc[0], pa, vb[0]);
                mma16(oacc[1], pa, vb[0] + 2);
                mma16(oacc[2], pa, vb[1]);
                mma16(oacc[3], pa, vb[1] + 2);

                int hcol = (2 * p + hh) * HD;
                __half* d0 = AOh + (w * NJ + gid) * TSTR + hcol + 2 * tig;
                #pragma unroll
                for (int j = 0; j < 4; j++)
                    *(__half2*)(d0 + j * 8) = __floats2half2_rn(oacc[j][0], oacc[j][1]);
                int r1 = gid + 8;
                if (r1 < NJ) {
                    __half* d1 = AOh + (w * NJ + r1) * TSTR + hcol + 2 * tig;
                    #pragma unroll
                    for (int j = 0; j < 4; j++)
                        *(__half2*)(d1 + j * 8) = __floats2half2_rn(oacc[j][2], oacc[j][3]);
                }
            }
        } else if (p == 1) {
            // warps 8..11: stage Wo rows 0..95 (ALL 16 chunks/row) into the dead X region
            int t2 = tid - 256;                     // 0..127
            #pragma unroll
            for (int j = 0; j < 12; j++) {
                int i = t2 + j * 128;               // < 1536
                int row = i >> 4, ch = (i & 15) * 8;   // 16 uint4 per 128-col row
                cpa16(sbX + (uint32_t)(row * TSTR) * 2 + ch * 2, gWo + row * DM + ch);
            }
            cp_commit();
            cp_wait0();
        }
        __syncthreads();   // QKV reads done (p0) / AO+Wo0-95 ready (p1)

        if (p == 0) {
            // stage W pass 1 (heads 2,3) via cp.async
            #pragma unroll
            for (int j = 0; j < 8; j++) {
                int i = tid + j * THREADS;          // < 3072
                int row = i >> 4, c = (i & 15) * 8;
                int hh  = row >= 96;
                int sub = (row - hh * 96) >> 5;
                cpa16(sbW + (uint32_t)(row * TSTR) * 2 + c * 2,
                      gWqkv + sub * 16384 + ((2 + hh) * HD + (row & 31)) * DM + c);
            }
            cp_commit();
            cp_wait0();
            __syncthreads();
        }
    }

    // ---- stage Wo rows 96..127 (16 chunks/row) into W region ----
    #pragma unroll
    for (int j = 0; j < 2; j++) {
        int i = tid + j * THREADS;
        if (i < 512) {
            int row = i >> 4, ch = (i & 15) * 8;    // row 0..31 -> Wo row 96+row
            cpa16(sbW + (uint32_t)(row * TSTR) * 2 + ch * 2, gWo + (96 + row) * DM + ch);
        }
    }
    cp_commit();
    cp_wait0();
    __syncthreads();

    // ===== final GEMM (12 warps, fm3 x fn4): Y(96x128) = AO @ Wo^T =====
    {
        const int fm = warp >> 2, fn = warp & 3;    // fm 0..2 (32 rows), fn 0..3 (32 cols)
        uint32_t faddr[2], fbaddr[2];
        #pragma unroll
        for (int i = 0; i < 2; i++)
            faddr[i] = sbAO + (uint32_t)((fm * 32 + i * 16 + (lane & 15)) * TSTR) * 2
                            + ((lane >> 4) * 16);
        #pragma unroll
        for (int j = 0; j < 2; j++) {
            int row = fn * 32 + j * 16 + (lane & 7) + ((lane >> 4) * 8);
            uint32_t base = (fn < 3) ? (sbX + (uint32_t)(row * TSTR) * 2)
                                     : (sbW + (uint32_t)((row - 96) * TSTR) * 2);
            fbaddr[j] = base + (((lane >> 3) & 1) * 16);
        }

        float y[2][4][4];
        #pragma unroll
        for (int i = 0; i < 2; i++)
            #pragma unroll
            for (int j = 0; j < 4; j++)
                #pragma unroll
                for (int r = 0; r < 4; r++) y[i][j][r] = 0.0f;

        #pragma unroll
        for (int ks = 0; ks < 8; ks++) {
            uint32_t a[2][4], b[2][4];
            #pragma unroll
            for (int i = 0; i < 2; i++) ldsm_x4(a[i], faddr[i] + ks * 32);
            #pragma unroll
            for (int j = 0; j < 2; j++) ldsm_x4(b[j], fbaddr[j] + ks * 32);
            #pragma unroll
            for (int i = 0; i < 2; i++)
                #pragma unroll
                for (int j = 0; j < 2; j++) {
                    mma16(y[i][2*j],   a[i], b[j]);
                    mma16(y[i][2*j+1], a[i], b[j] + 2);
                }
        }

        #pragma unroll
        for (int i = 0; i < 2; i++) {
            int row = fm * 32 + i * 16 + gid;
            #pragma unroll
            for (int j = 0; j < 4; j++) {
                int col = fn * 32 + j * 8 + 2 * tig;
                float b0 = bos[col], b1 = bos[col + 1];
                size_t base = ((size_t)cta * MR + row) * DM + col;
                *(float2*)(out + base)          = make_float2(y[i][j][0] + b0, y[i][j][1] + b1);
                *(float2*)(out + base + 8 * DM) = make_float2(y[i][j][2] + b0, y[i][j][3] + b1);
            }
        }
    }
}

extern "C" void kernel_launch(void* const* d_in, const int* in_sizes, int n_in,
                              void* d_out, int out_size) {
    const float* x   = (const float*)d_in[0];
    const float* vis = (const float*)d_in[1];
    const float* Wq  = (const float*)d_in[2];
    const float* bq  = (const float*)d_in[3];
    const float* Wk  = (const float*)d_in[4];
    const float* bk  = (const float*)d_in[5];
    const float* Wv  = (const float*)d_in[6];
    const float* bv  = (const float*)d_in[7];
    const float* Wo  = (const float*)d_in[8];
    const float* bo  = (const float*)d_in[9];
    const float* bsc = (const float*)d_in[10];
    const float* adj = (const float*)d_in[11];
    float* out = (float*)d_out;

    const int B = in_sizes[0] / (NJ * DM);      // 16384
    const int grid = B / TB;                    // 2048

    static bool attr_set = false;
    if (!attr_set) {
        cudaFuncSetAttribute(cross_joint_attn_kernel,
                             cudaFuncAttributeMaxDynamicSharedMemorySize, SMEM_BYTES);
        attr_set = true;
    }
    convert_weights<<<16, 256>>>(Wq, Wk, Wv, Wo);
    cross_joint_attn_kernel<<<grid, THREADS, SMEM_BYTES>>>(
        x, vis, bq, bk, bv, bo, bsc, adj, out);
}